// round 8
// baseline (speedup 1.0000x reference)
#include <cuda_runtime.h>
#include <cstddef>

// Problem constants
#define Bb 2
#define Ss 512
#define Hh 8
#define Dd 64
#define Ee 512          // H*D
#define QT 64           // q rows per block
#define NRU 256         // relative index r in [0,256)
#define EP  66          // sE pitch ([r][d] layout, conflict-free LDS.64; rows 8B-aligned)
#define PUP 257         // sPu pitch (odd -> conflict-free scalar access)

// ---- Fully fused kernel ----
// Grid = (8 qtiles, 16 b*h) = 128 blocks (one balanced wave), 512 threads.
// Phase 1: Pu[qi][r] = sum_d Q[b,q0+qi,h,d] * E[r, h*64+d]   (f32x2, d-parity packing)
//   Warp w = (qg = w>>1, rh = w&1): q rows {8qg..8qg+7}, r in {128rh + l + 32j}, j<4.
// Phase 2: out[b,h,q0+qi,k] = Pu[qi][ mx + x[b,k] - x[b,q0+qi] ]
__global__ __launch_bounds__(512)
void relpos_fused_kernel(const float* __restrict__ qin,
                         const float* __restrict__ et,
                         const int*   __restrict__ xw,
                         const int*   __restrict__ mxp,
                         float*       __restrict__ out)
{
    extern __shared__ float sm[];
    float* sE  = sm;                  // [NRU][EP]  E slice, row-major [r][d]  (67,584 B)
    float* sQ  = sm + NRU * EP;       // [QT][Dd]   row-major [q][d]           (16,384 B)
    float* sPu = sm;                  // [QT][PUP]  overlaid on sE after GEMM  (65,792 B)
    __shared__ int sX[Ss];
    __shared__ int sIs64;

    const int tid = threadIdx.x;
    const int q0  = blockIdx.x * QT;
    const int h   = blockIdx.y & 7;
    const int b   = blockIdx.y >> 3;

    // dtype detection: int64 x -> odd 32-bit words of the first 4 KB are all zero.
    if (tid == 0) sIs64 = 1;
    // E slice: float2 loads/stores (r*EP + 2k is even -> 8B aligned), coalesced.
    for (int i = tid; i < NRU * (Dd / 2); i += 512) {
        const int r = i >> 5, d2 = (i & 31) * 2;
        *(float2*)&sE[r * EP + d2] = *(const float2*)&et[r * Ee + h * Dd + d2];
    }
    // Q tile: float4, coalesced (row stride 64 -> 16B aligned).
    for (int i = tid; i < QT * (Dd / 4); i += 512) {
        const int qi = i >> 4, d4 = (i & 15) * 4;
        *(float4*)&sQ[qi * Dd + d4] = *(const float4*)&qin[(((size_t)b * Ss + q0 + qi) * Hh + h) * Dd + d4];
    }
    if (xw[2 * tid + 1] != 0) atomicAnd(&sIs64, 0);
    __syncthreads();

    // ---- Phase 1: GEMM, 8q x 4 r-pair-groups per warp ----
    const int l  = tid & 31;
    const int w  = tid >> 5;          // 0..15
    const int qg = w >> 1;            // q group: rows 8qg..8qg+7
    const int rh = (w & 1) * 128;     // r half

    unsigned long long acc[8][4];
    #pragma unroll
    for (int i = 0; i < 8; ++i)
        #pragma unroll
        for (int j = 0; j < 4; ++j) acc[i][j] = 0ULL;

    #pragma unroll 2
    for (int d = 0; d < Dd; d += 2) {
        unsigned long long e2[4], q2[8];
        #pragma unroll
        for (int j = 0; j < 4; ++j)   // LDS.64 (E[r][d], E[r][d+1]); stride-33-word rows: conflict-free
            e2[j] = *(const unsigned long long*)&sE[(rh + l + 32 * j) * EP + d];
        #pragma unroll
        for (int i = 0; i < 8; ++i)   // LDS.64 (q[d], q[d+1]); warp-broadcast
            q2[i] = *(const unsigned long long*)&sQ[(8 * qg + i) * Dd + d];
        #pragma unroll
        for (int i = 0; i < 8; ++i)
            #pragma unroll
            for (int j = 0; j < 4; ++j)
                asm("fma.rn.f32x2 %0, %1, %2, %3;"
                    : "=l"(acc[i][j]) : "l"(q2[i]), "l"(e2[j]), "l"(acc[i][j]));
    }
    __syncthreads();   // all warps done reading sE/sQ

    // ---- Stage Pu into smem (overlaid on sE); consecutive words per lane: conflict-free ----
    #pragma unroll
    for (int i = 0; i < 8; ++i)
        #pragma unroll
        for (int j = 0; j < 4; ++j) {
            float lo, hi;
            asm("mov.b64 {%0, %1}, %2;" : "=f"(lo), "=f"(hi) : "l"(acc[i][j]));
            sPu[(8 * qg + i) * PUP + rh + l + 32 * j] = lo + hi;
        }

    // x row for this batch, normalized to int32 (sIs64 valid since first sync).
    if (sIs64) sX[tid] = xw[2 * (b * Ss + tid)];
    else       sX[tid] = xw[b * Ss + tid];
    __syncthreads();

    // ---- Phase 2: epilogue scatter. Thread t: q row = t>>3, k quads strided by 8 ----
    const int mx  = mxp ? mxp[0] : 128;      // LE low word valid for int32/int64
    const int qi  = tid >> 3;                // 0..63
    const int kc  = tid & 7;                 // k-quad column
    const int off = mx - sX[q0 + qi];
    const float* p = &sPu[qi * PUP];
    float* orow = out + (((size_t)(b * Hh + h) * Ss + q0 + qi)) * Ss;

    #pragma unroll
    for (int it = 0; it < 16; ++it) {
        const int k0 = (kc + 8 * it) * 4;
        float4 v;
        v.x = p[off + sX[k0]];
        v.y = p[off + sX[k0 + 1]];
        v.z = p[off + sX[k0 + 2]];
        v.w = p[off + sX[k0 + 3]];
        *(float4*)&orow[k0] = v;             // STG.128, 64B-contiguous per 4-lane group
    }
}

extern "C" void kernel_launch(void* const* d_in, const int* in_sizes, int n_in,
                              void* d_out, int out_size) {
    const float* q   = (const float*)d_in[0];
    const float* et  = (const float*)d_in[1];
    const int*   xw  = (const int*)d_in[2];
    const int*   mxp = (n_in > 3) ? (const int*)d_in[3] : nullptr;
    float*       out = (float*)d_out;
    (void)in_sizes; (void)out_size;

    const int smem = (NRU * EP + QT * Dd) * sizeof(float);  // 83,968 B
    cudaFuncSetAttribute(relpos_fused_kernel,
                         cudaFuncAttributeMaxDynamicSharedMemorySize, smem);

    dim3 grid(Ss / QT, Hh * Bb);             // 8 x 16 = 128 blocks (one wave)
    relpos_fused_kernel<<<grid, 512, smem>>>(q, et, xw, mxp, out);
}

// round 9
// speedup vs baseline: 1.0118x; 1.0118x over previous
#include <cuda_runtime.h>
#include <cstddef>

// Problem constants
#define Bb 2
#define Ss 512
#define Hh 8
#define Dd 64
#define Ee 512          // H*D
#define QT 64           // q rows per block
#define NRU 256         // relative index r in [0,256)
#define EP  66          // sE pitch ([r][d] layout, conflict-free LDS.64; rows 8B-aligned)
#define PUP 257         // sPu pitch (odd -> conflict-free scalar access)

// ---- Fully fused kernel ----
// Grid = (8 qtiles, 16 b*h) = 128 blocks (one balanced wave), 512 threads.
// Phase 1: Pu[qi][r] = sum_d Q[b,q0+qi,h,d] * E[r, h*64+d]   (f32x2, d-parity packing)
//   Warp w = (qg = w>>1, rh = w&1): q rows {8qg..8qg+7}, r in {128rh + l + 32j}, j<4.
// Phase 2: out[b,h,q0+qi,k] = Pu[qi][ mx + x[b,k] - x[b,q0+qi] ]
__global__ __launch_bounds__(512)
void relpos_fused_kernel(const float* __restrict__ qin,
                         const float* __restrict__ et,
                         const int*   __restrict__ xw,
                         const int*   __restrict__ mxp,
                         float*       __restrict__ out)
{
    extern __shared__ float sm[];
    float* sE  = sm;                  // [NRU][EP]  E slice, row-major [r][d]  (67,584 B)
    float* sQ  = sm + NRU * EP;       // [QT][Dd]   row-major [q][d]           (16,384 B)
    float* sPu = sm;                  // [QT][PUP]  overlaid on sE after GEMM  (65,792 B)
    __shared__ int sX[Ss];
    __shared__ int sIs64;

    const int tid = threadIdx.x;
    const int q0  = blockIdx.x * QT;
    const int h   = blockIdx.y & 7;
    const int b   = blockIdx.y >> 3;

    // dtype detection: int64 x -> odd 32-bit words of the first 4 KB are all zero.
    if (tid == 0) sIs64 = 1;
    // E slice: float2 loads/stores (r*EP + 2k is even -> 8B aligned), coalesced.
    for (int i = tid; i < NRU * (Dd / 2); i += 512) {
        const int r = i >> 5, d2 = (i & 31) * 2;
        *(float2*)&sE[r * EP + d2] = *(const float2*)&et[r * Ee + h * Dd + d2];
    }
    // Q tile: float4, coalesced (row stride 64 -> 16B aligned).
    for (int i = tid; i < QT * (Dd / 4); i += 512) {
        const int qi = i >> 4, d4 = (i & 15) * 4;
        *(float4*)&sQ[qi * Dd + d4] = *(const float4*)&qin[(((size_t)b * Ss + q0 + qi) * Hh + h) * Dd + d4];
    }
    if (xw[2 * tid + 1] != 0) atomicAnd(&sIs64, 0);
    __syncthreads();

    // ---- Phase 1: GEMM, 8q x 4 r-pair-groups per warp ----
    const int l  = tid & 31;
    const int w  = tid >> 5;          // 0..15
    const int qg = w >> 1;            // q group: rows 8qg..8qg+7
    const int rh = (w & 1) * 128;     // r half

    unsigned long long acc[8][4];
    #pragma unroll
    for (int i = 0; i < 8; ++i)
        #pragma unroll
        for (int j = 0; j < 4; ++j) acc[i][j] = 0ULL;

    #pragma unroll 2
    for (int d = 0; d < Dd; d += 2) {
        unsigned long long e2[4], q2[8];
        #pragma unroll
        for (int j = 0; j < 4; ++j)   // LDS.64 (E[r][d], E[r][d+1]); stride-33-word rows: conflict-free
            e2[j] = *(const unsigned long long*)&sE[(rh + l + 32 * j) * EP + d];
        #pragma unroll
        for (int i = 0; i < 8; ++i)   // LDS.64 (q[d], q[d+1]); warp-broadcast
            q2[i] = *(const unsigned long long*)&sQ[(8 * qg + i) * Dd + d];
        #pragma unroll
        for (int i = 0; i < 8; ++i)
            #pragma unroll
            for (int j = 0; j < 4; ++j)
                asm("fma.rn.f32x2 %0, %1, %2, %3;"
                    : "=l"(acc[i][j]) : "l"(q2[i]), "l"(e2[j]), "l"(acc[i][j]));
    }
    __syncthreads();   // all warps done reading sE/sQ

    // ---- Stage Pu into smem (overlaid on sE); consecutive words per lane: conflict-free ----
    #pragma unroll
    for (int i = 0; i < 8; ++i)
        #pragma unroll
        for (int j = 0; j < 4; ++j) {
            float lo, hi;
            asm("mov.b64 {%0, %1}, %2;" : "=f"(lo), "=f"(hi) : "l"(acc[i][j]));
            sPu[(8 * qg + i) * PUP + rh + l + 32 * j] = lo + hi;
        }

    // x row for this batch, normalized to int32 (sIs64 valid since first sync).
    if (sIs64) sX[tid] = xw[2 * (b * Ss + tid)];
    else       sX[tid] = xw[b * Ss + tid];
    __syncthreads();

    // ---- Phase 2: epilogue scatter. Thread t: q row = t>>3, k quads strided by 8 ----
    const int mx  = mxp ? mxp[0] : 128;      // LE low word valid for int32/int64
    const int qi  = tid >> 3;                // 0..63
    const int kc  = tid & 7;                 // k-quad column
    const int off = mx - sX[q0 + qi];
    const float* p = &sPu[qi * PUP];
    float* orow = out + (((size_t)(b * Hh + h) * Ss + q0 + qi)) * Ss;

    #pragma unroll
    for (int it = 0; it < 16; ++it) {
        const int k0 = (kc + 8 * it) * 4;
        float4 v;
        v.x = p[off + sX[k0]];
        v.y = p[off + sX[k0 + 1]];
        v.z = p[off + sX[k0 + 2]];
        v.w = p[off + sX[k0 + 3]];
        *(float4*)&orow[k0] = v;             // STG.128, 64B-contiguous per 4-lane group
    }
}

extern "C" void kernel_launch(void* const* d_in, const int* in_sizes, int n_in,
                              void* d_out, int out_size) {
    const float* q   = (const float*)d_in[0];
    const float* et  = (const float*)d_in[1];
    const int*   xw  = (const int*)d_in[2];
    const int*   mxp = (n_in > 3) ? (const int*)d_in[3] : nullptr;
    float*       out = (float*)d_out;
    (void)in_sizes; (void)out_size;

    const int smem = (NRU * EP + QT * Dd) * sizeof(float);  // 83,968 B
    cudaFuncSetAttribute(relpos_fused_kernel,
                         cudaFuncAttributeMaxDynamicSharedMemorySize, smem);

    dim3 grid(Ss / QT, Hh * Bb);             // 8 x 16 = 128 blocks (one wave)
    relpos_fused_kernel<<<grid, 512, smem>>>(q, et, xw, mxp, out);
}

// round 11
// speedup vs baseline: 1.2937x; 1.2786x over previous
#include <cuda_runtime.h>
#include <cuda_bf16.h>
#include <cstdint>
#include <cstddef>

// Problem constants
#define Bb 2
#define Ss 512
#define Hh 8
#define Dd 64
#define Ee 512
#define QT 64            // q rows per block
#define NRU 256          // relative index r
#define ROWB 144         // bf16 tile row stride in BYTES (16B rotation -> ldmatrix conflict-free)
#define PUP 258          // sPu pitch (even -> float2-aligned staging)

// Dynamic smem offsets (bytes)
#define OFF_QHI 0
#define OFF_QLO (QT * ROWB)               //  9216
#define OFF_EHI (2 * QT * ROWB)           // 18432
#define OFF_ELO (2 * QT * ROWB + NRU * ROWB)  // 55296
#define DYN_BYTES (2 * QT * ROWB + 2 * NRU * ROWB)  // 92160; sPu (64*258*4=66048) overlays

__device__ __forceinline__ uint32_t smem_u32(const void* p) {
    uint32_t a;
    asm("{ .reg .u64 t; cvta.to.shared.u64 t, %1; cvt.u32.u64 %0, t; }" : "=r"(a) : "l"(p));
    return a;
}
__device__ __forceinline__ uint32_t pack2(float a, float b) {
    __nv_bfloat162 t = __floats2bfloat162_rn(a, b);   // .x = a (low half)
    return *reinterpret_cast<uint32_t*>(&t);
}
__device__ __forceinline__ void ldsm_x4(uint32_t (&r)[4], uint32_t addr) {
    asm volatile("ldmatrix.sync.aligned.m8n8.x4.shared.b16 {%0,%1,%2,%3}, [%4];"
                 : "=r"(r[0]), "=r"(r[1]), "=r"(r[2]), "=r"(r[3]) : "r"(addr));
}
__device__ __forceinline__ void ldsm_x2(uint32_t (&r)[2], uint32_t addr) {
    asm volatile("ldmatrix.sync.aligned.m8n8.x2.shared.b16 {%0,%1}, [%2];"
                 : "=r"(r[0]), "=r"(r[1]) : "r"(addr));
}
__device__ __forceinline__ void mma_bf16(float (&c)[4], const uint32_t (&a)[4],
                                         const uint32_t (&b)[2]) {
    asm volatile("mma.sync.aligned.m16n8k16.row.col.f32.bf16.bf16.f32 "
                 "{%0,%1,%2,%3}, {%4,%5,%6,%7}, {%8,%9}, {%0,%1,%2,%3};"
                 : "+f"(c[0]), "+f"(c[1]), "+f"(c[2]), "+f"(c[3])
                 : "r"(a[0]), "r"(a[1]), "r"(a[2]), "r"(a[3]), "r"(b[0]), "r"(b[1]));
}

// ---- Fused kernel, HMMA (mma.sync) GEMM core ----
// Grid = (8 qtiles, 16 b*h) = 128 blocks (one wave), 512 threads (16 warps).
// Phase 1: Pu[64,256] = Qhi·Ehi^T + Qhi·Elo^T + Qlo·Ehi^T  (split-bf16, fp32 acc)
// Phase 2: out[b,h,q0+qi,k] = Pu[qi][ mx + x[b,k] - x[b,q0+qi] ]
__global__ __launch_bounds__(512)
void relpos_hmma_kernel(const float* __restrict__ qin,
                        const float* __restrict__ et,
                        const int*   __restrict__ xw,
                        const int*   __restrict__ mxp,
                        float*       __restrict__ out)
{
    extern __shared__ char tiles[];
    __shared__ int sX[Ss];
    __shared__ int sIs64;

    const uint32_t tb = smem_u32(tiles);
    const int tid  = threadIdx.x;
    const int lane = tid & 31;
    const int w    = tid >> 5;
    const int q0   = blockIdx.x * QT;
    const int h    = blockIdx.y & 7;
    const int b    = blockIdx.y >> 3;

    if (tid == 0) sIs64 = 1;

    // ---- Load + split E (256 x 64) ----
    for (int i = tid; i < NRU * (Dd / 4); i += 512) {
        const int r = i >> 4, c4 = (i & 15) * 4;
        const float4 v = *(const float4*)&et[r * Ee + h * Dd + c4];
        const float hx = __bfloat162float(__float2bfloat16_rn(v.x));
        const float hy = __bfloat162float(__float2bfloat16_rn(v.y));
        const float hz = __bfloat162float(__float2bfloat16_rn(v.z));
        const float hw = __bfloat162float(__float2bfloat16_rn(v.w));
        const int off = r * ROWB + c4 * 2;
        *(uint2*)(tiles + OFF_EHI + off) = make_uint2(pack2(hx, hy), pack2(hz, hw));
        *(uint2*)(tiles + OFF_ELO + off) =
            make_uint2(pack2(v.x - hx, v.y - hy), pack2(v.z - hz, v.w - hw));
    }
    // ---- Load + split Q (64 x 64) ----
    for (int i = tid; i < QT * (Dd / 4); i += 512) {
        const int qi = i >> 4, c4 = (i & 15) * 4;
        const float4 v = *(const float4*)&qin[(((size_t)b * Ss + q0 + qi) * Hh + h) * Dd + c4];
        const float hx = __bfloat162float(__float2bfloat16_rn(v.x));
        const float hy = __bfloat162float(__float2bfloat16_rn(v.y));
        const float hz = __bfloat162float(__float2bfloat16_rn(v.z));
        const float hw = __bfloat162float(__float2bfloat16_rn(v.w));
        const int off = qi * ROWB + c4 * 2;
        *(uint2*)(tiles + OFF_QHI + off) = make_uint2(pack2(hx, hy), pack2(hz, hw));
        *(uint2*)(tiles + OFF_QLO + off) =
            make_uint2(pack2(v.x - hx, v.y - hy), pack2(v.z - hz, v.w - hw));
    }
    // dtype detection: int64 x -> odd 32-bit words of first 4 KB are all zero.
    if (xw[2 * tid + 1] != 0) atomicAnd(&sIs64, 0);
    __syncthreads();

    // x row, normalized to int32 (sIs64 settled at the barrier above)
    if (sIs64) sX[tid] = xw[2 * (b * Ss + tid)];
    else       sX[tid] = xw[b * Ss + tid];

    // ---- Phase 1: HMMA GEMM. warp w: m-tile mi = w>>2 (16 q rows), n-block nb = w&3 (64 r) ----
    const int mi = w >> 2;
    const int nb = w & 3;

    float acc[8][4];
    #pragma unroll
    for (int nt = 0; nt < 8; ++nt)
        #pragma unroll
        for (int c = 0; c < 4; ++c) acc[nt][c] = 0.0f;

    // ldmatrix lane addressing
    const uint32_t aAddrOff = (uint32_t)((mi * 16 + (lane & 15)) * ROWB + (lane >> 4) * 16);
    const uint32_t bRow     = (uint32_t)(lane & 7);
    const uint32_t bColOff  = (uint32_t)(((lane >> 3) & 1) * 16);

    #pragma unroll
    for (int kc = 0; kc < 4; ++kc) {           // K chunks of 16 (32 B)
        uint32_t ahi[4], alo[4];
        ldsm_x4(ahi, tb + OFF_QHI + aAddrOff + kc * 32);
        ldsm_x4(alo, tb + OFF_QLO + aAddrOff + kc * 32);
        #pragma unroll
        for (int nt = 0; nt < 8; ++nt) {
            const uint32_t eoff = (uint32_t)((nb * 64 + nt * 8 + bRow) * ROWB) + bColOff + kc * 32;
            uint32_t bhi[2], blo[2];
            ldsm_x2(bhi, tb + OFF_EHI + eoff);
            ldsm_x2(blo, tb + OFF_ELO + eoff);
            mma_bf16(acc[nt], ahi, bhi);
            mma_bf16(acc[nt], ahi, blo);
            mma_bf16(acc[nt], alo, bhi);
        }
    }
    __syncthreads();   // all warps done reading tiles before sPu overlay

    // ---- Stage Pu into smem (overlaying tiles) ----
    float* sPu = (float*)tiles;
    {
        const int row = mi * 16 + (lane >> 2);
        const int colb = nb * 64 + 2 * (lane & 3);
        #pragma unroll
        for (int nt = 0; nt < 8; ++nt) {
            const int col = colb + nt * 8;
            *(float2*)&sPu[row * PUP + col]       = make_float2(acc[nt][0], acc[nt][1]);
            *(float2*)&sPu[(row + 8) * PUP + col] = make_float2(acc[nt][2], acc[nt][3]);
        }
    }
    __syncthreads();

    // ---- Phase 2: scatter epilogue. Thread t: q row = t>>3, k quads kc2 + 8*it ----
    const int mx  = mxp ? mxp[0] : 128;        // LE low word valid for int32/int64
    const int qi  = tid >> 3;                  // 0..63
    const int kc2 = tid & 7;
    const int off = mx - sX[q0 + qi];
    const float* p = &sPu[qi * PUP];
    float* orow = out + (((size_t)(b * Hh + h) * Ss + q0 + qi)) * Ss;

    #pragma unroll
    for (int it = 0; it < 16; ++it) {
        const int k0 = (kc2 + 8 * it) * 4;
        float4 v;
        v.x = p[off + sX[k0]];
        v.y = p[off + sX[k0 + 1]];
        v.z = p[off + sX[k0 + 2]];
        v.w = p[off + sX[k0 + 3]];
        *(float4*)&orow[k0] = v;               // coalesced STG.128
    }
}

extern "C" void kernel_launch(void* const* d_in, const int* in_sizes, int n_in,
                              void* d_out, int out_size) {
    const float* q   = (const float*)d_in[0];
    const float* et  = (const float*)d_in[1];
    const int*   xw  = (const int*)d_in[2];
    const int*   mxp = (n_in > 3) ? (const int*)d_in[3] : nullptr;
    float*       out = (float*)d_out;
    (void)in_sizes; (void)out_size;

    cudaFuncSetAttribute(relpos_hmma_kernel,
                         cudaFuncAttributeMaxDynamicSharedMemorySize, DYN_BYTES);

    dim3 grid(Ss / QT, Hh * Bb);              // 8 x 16 = 128 blocks (one wave)
    relpos_hmma_kernel<<<grid, 512, DYN_BYTES>>>(q, et, xw, mxp, out);
}

// round 12
// speedup vs baseline: 1.4975x; 1.1575x over previous
#include <cuda_runtime.h>
#include <cuda_bf16.h>
#include <cstdint>
#include <cstddef>

// Problem constants
#define Bb 2
#define Ss 512
#define Hh 8
#define Dd 64
#define Ee 512
#define QT 64            // q rows per block
#define NRU 256          // relative index r
#define ROWB 144         // bf16 tile row stride in BYTES (16B rotation -> ldmatrix conflict-free)
#define PUP 258          // sPu pitch (even -> float2-aligned staging)
#define NT 1024          // threads per block

// Dynamic smem offsets (bytes)
#define OFF_QHI 0
#define OFF_QLO (QT * ROWB)                   //  9216
#define OFF_EHI (2 * QT * ROWB)               // 18432
#define OFF_ELO (2 * QT * ROWB + NRU * ROWB)  // 55296
#define DYN_BYTES (2 * QT * ROWB + 2 * NRU * ROWB)  // 92160; sPu (64*258*4=66048) overlays

__device__ __forceinline__ uint32_t smem_u32(const void* p) {
    uint32_t a;
    asm("{ .reg .u64 t; cvta.to.shared.u64 t, %1; cvt.u32.u64 %0, t; }" : "=r"(a) : "l"(p));
    return a;
}
__device__ __forceinline__ uint32_t pack2(float a, float b) {
    __nv_bfloat162 t = __floats2bfloat162_rn(a, b);   // .x = a (low half)
    return *reinterpret_cast<uint32_t*>(&t);
}
__device__ __forceinline__ void ldsm_x4(uint32_t (&r)[4], uint32_t addr) {
    asm volatile("ldmatrix.sync.aligned.m8n8.x4.shared.b16 {%0,%1,%2,%3}, [%4];"
                 : "=r"(r[0]), "=r"(r[1]), "=r"(r[2]), "=r"(r[3]) : "r"(addr));
}
__device__ __forceinline__ void ldsm_x2(uint32_t (&r)[2], uint32_t addr) {
    asm volatile("ldmatrix.sync.aligned.m8n8.x2.shared.b16 {%0,%1}, [%2];"
                 : "=r"(r[0]), "=r"(r[1]) : "r"(addr));
}
__device__ __forceinline__ void mma_bf16(float (&c)[4], const uint32_t (&a)[4],
                                         const uint32_t (&b)[2]) {
    asm volatile("mma.sync.aligned.m16n8k16.row.col.f32.bf16.bf16.f32 "
                 "{%0,%1,%2,%3}, {%4,%5,%6,%7}, {%8,%9}, {%0,%1,%2,%3};"
                 : "+f"(c[0]), "+f"(c[1]), "+f"(c[2]), "+f"(c[3])
                 : "r"(a[0]), "r"(a[1]), "r"(a[2]), "r"(a[3]), "r"(b[0]), "r"(b[1]));
}

// ---- Fused kernel, HMMA core, 1024 threads (32 warps) ----
// Grid = (8 qtiles, 16 b*h) = 128 blocks (one wave).
// Phase 1: Pu[64,256] = Qhi·Ehi^T + Qhi·Elo^T + Qlo·Ehi^T  (split-bf16, fp32 acc)
// Phase 2: out[b,h,q0+qi,k] = Pu[qi][ mx + x[b,k] - x[b,q0+qi] ]
__global__ __launch_bounds__(NT)
void relpos_hmma_kernel(const float* __restrict__ qin,
                        const float* __restrict__ et,
                        const int*   __restrict__ xw,
                        const int*   __restrict__ mxp,
                        float*       __restrict__ out)
{
    extern __shared__ char tiles[];
    __shared__ int sX[Ss];
    __shared__ int sIs64;

    const uint32_t tb = smem_u32(tiles);
    const int tid  = threadIdx.x;
    const int lane = tid & 31;
    const int w    = tid >> 5;            // 0..31
    const int q0   = blockIdx.x * QT;
    const int h    = blockIdx.y & 7;
    const int b    = blockIdx.y >> 3;

    if (tid == 0) sIs64 = 1;

    // ---- Load + split E (256 x 64) ----
    #pragma unroll
    for (int i = tid; i < NRU * (Dd / 4); i += NT) {
        const int r = i >> 4, c4 = (i & 15) * 4;
        const float4 v = *(const float4*)&et[r * Ee + h * Dd + c4];
        const float hx = __bfloat162float(__float2bfloat16_rn(v.x));
        const float hy = __bfloat162float(__float2bfloat16_rn(v.y));
        const float hz = __bfloat162float(__float2bfloat16_rn(v.z));
        const float hw = __bfloat162float(__float2bfloat16_rn(v.w));
        const int off = r * ROWB + c4 * 2;
        *(uint2*)(tiles + OFF_EHI + off) = make_uint2(pack2(hx, hy), pack2(hz, hw));
        *(uint2*)(tiles + OFF_ELO + off) =
            make_uint2(pack2(v.x - hx, v.y - hy), pack2(v.z - hz, v.w - hw));
    }
    // ---- Load + split Q (64 x 64) ----
    {
        const int i = tid;                 // exactly 1024 quads
        const int qi = i >> 4, c4 = (i & 15) * 4;
        const float4 v = *(const float4*)&qin[(((size_t)b * Ss + q0 + qi) * Hh + h) * Dd + c4];
        const float hx = __bfloat162float(__float2bfloat16_rn(v.x));
        const float hy = __bfloat162float(__float2bfloat16_rn(v.y));
        const float hz = __bfloat162float(__float2bfloat16_rn(v.z));
        const float hw = __bfloat162float(__float2bfloat16_rn(v.w));
        const int off = qi * ROWB + c4 * 2;
        *(uint2*)(tiles + OFF_QHI + off) = make_uint2(pack2(hx, hy), pack2(hz, hw));
        *(uint2*)(tiles + OFF_QLO + off) =
            make_uint2(pack2(v.x - hx, v.y - hy), pack2(v.z - hz, v.w - hw));
    }
    // dtype detection: int64 x -> odd 32-bit words of first 4 KB are all zero.
    if (tid < Ss && xw[2 * tid + 1] != 0) atomicAnd(&sIs64, 0);
    __syncthreads();

    // x row, normalized to int32 (sIs64 settled at the barrier above)
    if (tid < Ss) {
        if (sIs64) sX[tid] = xw[2 * (b * Ss + tid)];
        else       sX[tid] = xw[b * Ss + tid];
    }

    // ---- Phase 1: HMMA GEMM. warp w: m-tile mi = w>>3 (16 q), n-block nb = w&7 (32 r) ----
    const int mi = w >> 3;
    const int nb = w & 7;

    float acc[4][4];
    #pragma unroll
    for (int nt = 0; nt < 4; ++nt)
        #pragma unroll
        for (int c = 0; c < 4; ++c) acc[nt][c] = 0.0f;

    const uint32_t aAddrOff = (uint32_t)((mi * 16 + (lane & 15)) * ROWB + (lane >> 4) * 16);
    const uint32_t bRow     = (uint32_t)(lane & 7);
    const uint32_t bColOff  = (uint32_t)(((lane >> 3) & 1) * 16);

    #pragma unroll
    for (int kc = 0; kc < 4; ++kc) {           // K chunks of 16 (32 B)
        uint32_t ahi[4], alo[4];
        ldsm_x4(ahi, tb + OFF_QHI + aAddrOff + kc * 32);
        ldsm_x4(alo, tb + OFF_QLO + aAddrOff + kc * 32);
        #pragma unroll
        for (int nt = 0; nt < 4; ++nt) {
            const uint32_t eoff = (uint32_t)((nb * 32 + nt * 8 + bRow) * ROWB) + bColOff + kc * 32;
            uint32_t bhi[2], blo[2];
            ldsm_x2(bhi, tb + OFF_EHI + eoff);
            ldsm_x2(blo, tb + OFF_ELO + eoff);
            mma_bf16(acc[nt], ahi, bhi);
            mma_bf16(acc[nt], ahi, blo);
            mma_bf16(acc[nt], alo, bhi);
        }
    }
    __syncthreads();   // all warps done reading tiles before sPu overlay

    // ---- Stage Pu into smem (overlaying tiles) ----
    float* sPu = (float*)tiles;
    {
        const int row  = mi * 16 + (lane >> 2);
        const int colb = nb * 32 + 2 * (lane & 3);
        #pragma unroll
        for (int nt = 0; nt < 4; ++nt) {
            const int col = colb + nt * 8;
            *(float2*)&sPu[row * PUP + col]       = make_float2(acc[nt][0], acc[nt][1]);
            *(float2*)&sPu[(row + 8) * PUP + col] = make_float2(acc[nt][2], acc[nt][3]);
        }
    }
    __syncthreads();

    // ---- Phase 2: scatter epilogue. Thread t: q row = t>>4, k quads kc2 + 16*it ----
    const int mx  = mxp ? mxp[0] : 128;        // LE low word valid for int32/int64
    const int qi  = tid >> 4;                  // 0..63
    const int kc2 = tid & 15;
    const int off = mx - sX[q0 + qi];
    const float* p = &sPu[qi * PUP];
    float* orow = out + (((size_t)(b * Hh + h) * Ss + q0 + qi)) * Ss;

    #pragma unroll
    for (int it = 0; it < 8; ++it) {
        const int k0 = (kc2 + 16 * it) * 4;
        float4 v;
        v.x = p[off + sX[k0]];
        v.y = p[off + sX[k0 + 1]];
        v.z = p[off + sX[k0 + 2]];
        v.w = p[off + sX[k0 + 3]];
        *(float4*)&orow[k0] = v;               // coalesced STG.128
    }
}

extern "C" void kernel_launch(void* const* d_in, const int* in_sizes, int n_in,
                              void* d_out, int out_size) {
    const float* q   = (const float*)d_in[0];
    const float* et  = (const float*)d_in[1];
    const int*   xw  = (const int*)d_in[2];
    const int*   mxp = (n_in > 3) ? (const int*)d_in[3] : nullptr;
    float*       out = (float*)d_out;
    (void)in_sizes; (void)out_size;

    cudaFuncSetAttribute(relpos_hmma_kernel,
                         cudaFuncAttributeMaxDynamicSharedMemorySize, DYN_BYTES);

    dim3 grid(Ss / QT, Hh * Bb);              // 8 x 16 = 128 blocks (one wave)
    relpos_hmma_kernel<<<grid, NT, DYN_BYTES>>>(q, et, xw, mxp, out);
}